// round 15
// baseline (speedup 1.0000x reference)
#include <cuda_runtime.h>
#include <cuda_bf16.h>
#include <cuda_fp16.h>
#include <cstdint>

#define BB 8
#define TT 2048
#define DD 1024
#define HH 128
#define STG2 30720
#define STG3 40960

// ---- static scratch (allocation-free) ----
__device__ __half g_xh[BB * TT * DD];                      // x fp16 (A-side)
__device__ __half g_Wh[DD * 384], g_Wl[DD * 384];          // 32*W split [k][w*128+n]
__device__ float g_bias[384];
__device__ __half g_Qh[BB * TT * HH], g_Ql[BB * TT * HH];  // 256*Q split
__device__ __half g_Kh[BB * TT * HH], g_Kl[BB * TT * HH];  // 16*K split
__device__ float g_E[(size_t)BB * TT * TT];                // exp(att), fp32, 0 below diag
__device__ __half g_Vh[BB * TT * HH];                      // V fp16 (written by proj)
__device__ float g_invd[BB * TT];                          // 1/d[k]
__device__ float g_d[BB * TT];

// ---- helpers ----
__device__ __forceinline__ void hsplit(float x, __half& h, __half& l) {
    h = __float2half(x);
    l = __float2half(x - __half2float(h));
}
__device__ __forceinline__ uint32_t s2u(const void* p) {
    uint32_t a;
    asm("{ .reg .u64 t; cvta.to.shared.u64 t, %1; cvt.u32.u64 %0, t; }" : "=r"(a) : "l"(p));
    return a;
}
__device__ __forceinline__ void cpa16(uint32_t dst, const void* src) {
    asm volatile("cp.async.cg.shared.global [%0], [%1], 16;" :: "r"(dst), "l"(src));
}
__device__ __forceinline__ void cp_commit() { asm volatile("cp.async.commit_group;"); }
__device__ __forceinline__ void cp_wait1() { asm volatile("cp.async.wait_group 1;"); }
__device__ __forceinline__ void cp_wait0() { asm volatile("cp.async.wait_group 0;"); }
__device__ __forceinline__ void ldm_x4(uint32_t* r, uint32_t a) {
    asm volatile("ldmatrix.sync.aligned.m8n8.x4.shared.b16 {%0,%1,%2,%3},[%4];"
                 : "=r"(r[0]), "=r"(r[1]), "=r"(r[2]), "=r"(r[3]) : "r"(a));
}
__device__ __forceinline__ void ldm_x4t(uint32_t* r, uint32_t a) {
    asm volatile("ldmatrix.sync.aligned.m8n8.x4.trans.shared.b16 {%0,%1,%2,%3},[%4];"
                 : "=r"(r[0]), "=r"(r[1]), "=r"(r[2]), "=r"(r[3]) : "r"(a));
}
__device__ __forceinline__ void mmah(float* c, const uint32_t* a, const uint32_t* b) {
    asm volatile(
        "mma.sync.aligned.m16n8k16.row.col.f32.f16.f16.f32 "
        "{%0,%1,%2,%3},{%4,%5,%6,%7},{%8,%9},{%0,%1,%2,%3};"
        : "+f"(c[0]), "+f"(c[1]), "+f"(c[2]), "+f"(c[3])
        : "r"(a[0]), "r"(a[1]), "r"(a[2]), "r"(a[3]), "r"(b[0]), "r"(b[1]));
}

// ================= fp16 2-pass pipeline (proj), 2-stage =================
// stage: A hi [128m][32k] rows 80B @0; Bh @+10240 (272B rows); Bl @+20480.
__device__ __forceinline__ void ld_chunk2(const __half* A, int lda,
                                          const __half* Bh, const __half* Bl, int ldb,
                                          uint32_t sb, int tid) {
#pragma unroll
    for (int j = 0; j < 2; j++) {
        int e = tid + j * 256;
        int r = e >> 2, seg = e & 3;
        cpa16(sb + r * 80 + seg * 16, A + (size_t)r * lda + seg * 8);
    }
#pragma unroll
    for (int j = 0; j < 2; j++) {
        int e = tid + j * 256;
        int r = e >> 4, seg = e & 15;
        size_t so = (size_t)r * ldb + seg * 8;
        uint32_t d = sb + 10240 + r * 272 + seg * 16;
        cpa16(d, Bh + so);
        cpa16(d + 10240, Bl + so);
    }
}

__device__ __forceinline__ void compute_chunk2(uint32_t sb, float acc[4][4][4],
                                               int lane, int wm, int wn) {
    const int g = lane >> 3, lr = lane & 7;
#pragma unroll
    for (int ks = 0; ks < 2; ks++) {
        uint32_t bh[4][2], bl[4][2];
#pragma unroll
        for (int np = 0; np < 2; np++) {
            uint32_t ba = sb + 10240 + (ks * 16 + (g & 1) * 8 + lr) * 272 +
                          (wn * 32 + np * 16 + (g >> 1) * 8) * 2;
            uint32_t r[4];
            ldm_x4t(r, ba);
            bh[np * 2][0] = r[0]; bh[np * 2][1] = r[1];
            bh[np * 2 + 1][0] = r[2]; bh[np * 2 + 1][1] = r[3];
            ldm_x4t(r, ba + 10240);
            bl[np * 2][0] = r[0]; bl[np * 2][1] = r[1];
            bl[np * 2 + 1][0] = r[2]; bl[np * 2 + 1][1] = r[3];
        }
        uint32_t af[2][4];
        ldm_x4(af[0], sb + (wm * 64 + (lane & 15)) * 80 + ks * 32 + (lane >> 4) * 16);
#pragma unroll
        for (int mt = 0; mt < 4; mt++) {
            if (mt < 3)
                ldm_x4(af[(mt + 1) & 1],
                       sb + (wm * 64 + (mt + 1) * 16 + (lane & 15)) * 80 + ks * 32 + (lane >> 4) * 16);
            const uint32_t* a = af[mt & 1];
#pragma unroll
            for (int nt = 0; nt < 4; nt++) mmah(acc[mt][nt], a, bh[nt]);
#pragma unroll
            for (int nt = 0; nt < 4; nt++) mmah(acc[mt][nt], a, bl[nt]);
        }
    }
}

__device__ __forceinline__ void gemm_pipe2(const __half* A, int lda,
                                           const __half* Bh, const __half* Bl, int ldb,
                                           int n, size_t aStep, size_t bStep,
                                           uint32_t sb, float acc[4][4][4], int tid) {
    const int lane = tid & 31, wid = tid >> 5;
    const int wm = wid >> 2, wn = wid & 3;
    ld_chunk2(A, lda, Bh, Bl, ldb, sb, tid);
    cp_commit();
    for (int i = 0; i < n; i++) {
        if (i + 1 < n) {
            ld_chunk2(A + (i + 1) * aStep, lda,
                      Bh + (i + 1) * bStep, Bl + (i + 1) * bStep, ldb,
                      sb + ((i + 1) & 1) * STG2, tid);
            cp_commit();
            cp_wait1();
        } else {
            cp_wait0();
        }
        __syncthreads();
        compute_chunk2(sb + (i & 1) * STG2, acc, lane, wm, wn);
        __syncthreads();
    }
}

// ================= fp16 3-pass pipeline (scores), 2-stage =================
__device__ __forceinline__ void ld_chunk3(const __half* Ah, const __half* Al, int lda,
                                          const __half* Bh, const __half* Bl, int ldb,
                                          uint32_t sb, int tid) {
#pragma unroll
    for (int j = 0; j < 2; j++) {
        int e = tid + j * 256;
        int r = e >> 2, seg = e & 3;
        size_t so = (size_t)r * lda + seg * 8;
        uint32_t d = sb + r * 80 + seg * 16;
        cpa16(d, Ah + so);
        cpa16(d + 10240, Al + so);
    }
#pragma unroll
    for (int j = 0; j < 2; j++) {
        int e = tid + j * 256;
        int r = e >> 2, seg = e & 3;
        size_t so = (size_t)r * ldb + seg * 8;
        uint32_t d = sb + 20480 + r * 80 + seg * 16;
        cpa16(d, Bh + so);
        cpa16(d + 10240, Bl + so);
    }
}

__device__ __forceinline__ void compute_chunk3(uint32_t sb, float acc[4][4][4],
                                               int lane, int wm, int wn) {
    const int g = lane >> 3, lr = lane & 7;
#pragma unroll
    for (int ks = 0; ks < 2; ks++) {
        uint32_t bh[4][2], bl[4][2];
#pragma unroll
        for (int np = 0; np < 2; np++) {
            int nrow = wn * 32 + np * 16 + (g >> 1) * 8 + lr;
            uint32_t ba = sb + 20480 + nrow * 80 + ks * 32 + (g & 1) * 16;
            uint32_t r[4];
            ldm_x4(r, ba);
            bh[np * 2][0] = r[0]; bh[np * 2][1] = r[1];
            bh[np * 2 + 1][0] = r[2]; bh[np * 2 + 1][1] = r[3];
            ldm_x4(r, ba + 10240);
            bl[np * 2][0] = r[0]; bl[np * 2][1] = r[1];
            bl[np * 2 + 1][0] = r[2]; bl[np * 2 + 1][1] = r[3];
        }
        uint32_t af[2][4];
        ldm_x4(af[0], sb + (wm * 64 + (lane & 15)) * 80 + ks * 32 + (lane >> 4) * 16);
#pragma unroll
        for (int mt = 0; mt < 4; mt++) {
            if (mt < 3)
                ldm_x4(af[(mt + 1) & 1],
                       sb + (wm * 64 + (mt + 1) * 16 + (lane & 15)) * 80 + ks * 32 + (lane >> 4) * 16);
            const uint32_t* a = af[mt & 1];
#pragma unroll
            for (int nt = 0; nt < 4; nt++) mmah(acc[mt][nt], a, bh[nt]);
#pragma unroll
            for (int nt = 0; nt < 4; nt++) mmah(acc[mt][nt], a, bl[nt]);
        }
        ldm_x4(af[0], sb + 10240 + (wm * 64 + (lane & 15)) * 80 + ks * 32 + (lane >> 4) * 16);
#pragma unroll
        for (int mt = 0; mt < 4; mt++) {
            if (mt < 3)
                ldm_x4(af[(mt + 1) & 1],
                       sb + 10240 + (wm * 64 + (mt + 1) * 16 + (lane & 15)) * 80 + ks * 32 + (lane >> 4) * 16);
            const uint32_t* a = af[mt & 1];
#pragma unroll
            for (int nt = 0; nt < 4; nt++) mmah(acc[mt][nt], a, bh[nt]);
        }
    }
}

__device__ __forceinline__ void gemm_pipe3(const __half* Ah, const __half* Al, int lda,
                                           const __half* Bh, const __half* Bl, int ldb,
                                           int n, size_t aStep, size_t bStep,
                                           uint32_t sb, float acc[4][4][4], int tid) {
    const int lane = tid & 31, wid = tid >> 5;
    const int wm = wid >> 2, wn = wid & 3;
    ld_chunk3(Ah, Al, lda, Bh, Bl, ldb, sb, tid);
    cp_commit();
    for (int i = 0; i < n; i++) {
        if (i + 1 < n) {
            ld_chunk3(Ah + (i + 1) * aStep, Al + (i + 1) * aStep, lda,
                      Bh + (i + 1) * bStep, Bl + (i + 1) * bStep, ldb,
                      sb + ((i + 1) & 1) * STG3, tid);
            cp_commit();
            cp_wait1();
        } else {
            cp_wait0();
        }
        __syncthreads();
        compute_chunk3(sb + (i & 1) * STG3, acc, lane, wm, wn);
        __syncthreads();
    }
}

// ---- convert kernels ----
__global__ void convx_kernel(const float* __restrict__ x) {
    size_t i = ((size_t)blockIdx.x * 256 + threadIdx.x) * 8;
#pragma unroll
    for (int j = 0; j < 2; j++) {
        float4 v = *(const float4*)&x[i + j * 4];
        *(__half2*)&g_xh[i + j * 4] = {__float2half(v.x), __float2half(v.y)};
        *(__half2*)&g_xh[i + j * 4 + 2] = {__float2half(v.z), __float2half(v.w)};
    }
}
__global__ void convw_kernel(const float* __restrict__ Wq, const float* __restrict__ Wk,
                             const float* __restrict__ Wv, const float* __restrict__ bq,
                             const float* __restrict__ bk, const float* __restrict__ bv) {
    int i = blockIdx.x * 256 + threadIdx.x;
    int w = i / (DD * HH), rem = i % (DD * HH);
    int r = rem / HH, c = rem % HH;
    const float* W = (w == 0) ? Wq : (w == 1) ? Wk : Wv;
    float v = W[(size_t)r * HH + c] * 32.0f;
    __half h, l;
    hsplit(v, h, l);
    g_Wh[(size_t)r * 384 + w * 128 + c] = h;
    g_Wl[(size_t)r * 384 + w * 128 + c] = l;
    if (i < 384)
        g_bias[i] = (i < 128) ? bq[i] : (i < 256) ? bk[i - 128] : bv[i - 256];
}
__global__ void invd_kernel() {
    int i = blockIdx.x * 256 + threadIdx.x;   // over BB*TT
    g_invd[i] = 1.0f / g_d[i];
}

// ---- stage 1: projections (fp16 2-pass, 2-stage) ----
__global__ void __launch_bounds__(256, 2) proj_kernel() {
    extern __shared__ char sm[];
    const uint32_t sb = s2u(sm);
    const int tid = threadIdx.x, lane = tid & 31, wid = tid >> 5;
    const int wm = wid >> 2, wn = wid & 3;
    const int w = blockIdx.x, m0 = blockIdx.y * 128;
    float acc[4][4][4] = {};
    gemm_pipe2(g_xh + (size_t)m0 * DD, DD,
               g_Wh + w * 128, g_Wl + w * 128, 384,
               32, 32, (size_t)32 * 384, sb, acc, tid);
    const float* bias = g_bias + w * 128;
#pragma unroll
    for (int mt = 0; mt < 4; mt++)
#pragma unroll
        for (int nt = 0; nt < 4; nt++)
#pragma unroll
            for (int h = 0; h < 2; h++) {
                int row = wm * 64 + mt * 16 + (lane >> 2) + h * 8;
                int col = wn * 32 + nt * 8 + (lane & 3) * 2;
                size_t gm = (size_t)(m0 + row);
                float v0 = acc[mt][nt][h * 2] * 0.03125f + bias[col];      // /32
                float v1 = acc[mt][nt][h * 2 + 1] * 0.03125f + bias[col + 1];
                if (w == 2) {
                    *(__half2*)&g_Vh[gm * HH + col] = {__float2half(v0), __float2half(v1)};
                } else if (w == 0) {
                    __half h0, l0, h1, l1;
                    hsplit(v0 * 256.0f, h0, l0);
                    hsplit(v1 * 256.0f, h1, l1);
                    *(__half2*)&g_Qh[gm * HH + col] = {h0, h1};
                    *(__half2*)&g_Ql[gm * HH + col] = {l0, l1};
                } else {
                    __half h0, l0, h1, l1;
                    hsplit(v0 * 16.0f, h0, l0);
                    hsplit(v1 * 16.0f, h1, l1);
                    *(__half2*)&g_Kh[gm * HH + col] = {h0, h1};
                    *(__half2*)&g_Kl[gm * HH + col] = {l0, l1};
                }
            }
}

// ---- stage 2: scores (fp16 3-pass; E fp32; compacted upper-tri grid) ----
__global__ void __launch_bounds__(256, 2) scores_kernel() {
    const int t = blockIdx.x, b = blockIdx.z;
    int kT = (int)((sqrtf(8.0f * t + 1.0f) - 1.0f) * 0.5f);
    while (kT * (kT + 1) / 2 > t) kT--;
    while ((kT + 1) * (kT + 2) / 2 <= t) kT++;
    const int qT = t - kT * (kT + 1) / 2;
    extern __shared__ char sm[];
    const uint32_t sb = s2u(sm);
    const int tid = threadIdx.x, lane = tid & 31, wid = tid >> 5;
    const int wm = wid >> 2, wn = wid & 3;
    const int q0 = qT * 128, k0 = kT * 128;
    const size_t mq = (size_t)b * TT + q0, mk = (size_t)b * TT + k0;
    float acc[4][4][4] = {};
    gemm_pipe3(g_Qh + mq * HH, g_Ql + mq * HH, HH,
               g_Kh + mk * HH, g_Kl + mk * HH, HH,
               4, 32, 32, sb, acc, tid);
    float* se = (float*)sm;  // [128][136]
#pragma unroll
    for (int mt = 0; mt < 4; mt++)
#pragma unroll
        for (int nt = 0; nt < 4; nt++)
#pragma unroll
            for (int h = 0; h < 2; h++) {
                int row = wm * 64 + mt * 16 + (lane >> 2) + h * 8;
                int col = wn * 32 + nt * 8 + (lane & 3) * 2;
                int q = q0 + row;
                float a0 = acc[mt][nt][h * 2] * 2.44140625e-4f;        // /(256*16)
                float a1 = acc[mt][nt][h * 2 + 1] * 2.44140625e-4f;
                se[row * 136 + col] = (q <= k0 + col) ? __expf(a0) : 0.f;
                se[row * 136 + col + 1] = (q <= k0 + col + 1) ? __expf(a1) : 0.f;
            }
    __syncthreads();
    if (tid < 128) {
        float s = 0.f;
#pragma unroll 8
        for (int r = 0; r < 128; r++) s += se[r * 136 + tid];
        atomicAdd(&g_d[b * TT + k0 + tid], s);
    }
    float* Eb = g_E + (size_t)b * TT * TT;
#pragma unroll 4
    for (int i = 0; i < 16; i++) {
        int e = tid + i * 256;
        int q = e >> 5, c4 = (e & 31) * 4;
        *(float4*)&Eb[(size_t)(q0 + q) * TT + k0 + c4] = *(float4*)&se[q * 136 + c4];
    }
}

// ---- stage 3: out = (E/d) @ V, 1-pass fp16, 8-way split-k, atomics ----
// smem: invd[2048]f @0 (8192B); 2 stages of (A 10240 + B 8704) @8192, stride 18944.
__global__ void __launch_bounds__(256, 2) out_kernel(float* __restrict__ Out) {
    const int seg = blockIdx.x, qT = blockIdx.y, b = blockIdx.z;
    extern __shared__ char sm[];
    const uint32_t sb = s2u(sm);
    const int tid = threadIdx.x, lane = tid & 31, wid = tid >> 5;
    const int wm = wid >> 2, wn = wid & 3;
    const int q0 = qT * 128;
    const int c0 = q0 / 32 + seg;
    const int nch = (TT - q0) / 32;
    const int nIter = (nch - seg + 7) / 8;
    if (nIter <= 0) return;

    float* invd_s = (float*)sm;
    for (int i = tid; i < TT; i += 256) invd_s[i] = g_invd[b * TT + i];

    const float* Eb = g_E + ((size_t)b * TT + q0) * TT;
    const __half* Vb = g_Vh + (size_t)b * TT * HH;

    float er[2][8];
    auto ldE = [&](int i) {
        int kk = (c0 + i * 8) * 32;
#pragma unroll
        for (int j = 0; j < 2; j++) {
            int e = tid + j * 256;
            int r = e >> 2, s8 = (e & 3) * 8;
            const float* p = Eb + (size_t)r * TT + kk + s8;
            float4 v0 = *(const float4*)p;
            float4 v1 = *(const float4*)(p + 4);
            er[j][0] = v0.x; er[j][1] = v0.y; er[j][2] = v0.z; er[j][3] = v0.w;
            er[j][4] = v1.x; er[j][5] = v1.y; er[j][6] = v1.z; er[j][7] = v1.w;
        }
    };
    auto ldV = [&](int i, int st) {
#pragma unroll
        for (int j = 0; j < 2; j++) {
            int e = tid + j * 256;
            int r = e >> 4, sg = e & 15;
            cpa16(sb + 8192 + st * 18944 + 10240 + r * 272 + sg * 16,
                  Vb + ((size_t)((c0 + i * 8) * 32 + r)) * HH + sg * 8);
        }
    };

    ldE(0);
    ldV(0, 0);
    cp_commit();

    float acc[4][4][4] = {};
    for (int i = 0; i < nIter; i++) {
        const int st = i & 1;
        cp_wait0();
        __syncthreads();
        {
            int kk = (c0 + i * 8) * 32;
#pragma unroll
            for (int j = 0; j < 2; j++) {
                int e = tid + j * 256;
                int r = e >> 2, s8 = (e & 3) * 8;
                __half2 hx[4];
#pragma unroll
                for (int p2 = 0; p2 < 4; p2++) {
                    float a0 = er[j][p2 * 2] * invd_s[kk + s8 + p2 * 2];
                    float a1 = er[j][p2 * 2 + 1] * invd_s[kk + s8 + p2 * 2 + 1];
                    hx[p2] = __floats2half2_rn(a0, a1);
                }
                *(uint4*)(sm + 8192 + st * 18944 + r * 80 + s8 * 2) = *(uint4*)hx;
            }
        }
        if (i + 1 < nIter) ldE(i + 1);
        __syncthreads();
        if (i + 1 < nIter) { ldV(i + 1, st ^ 1); cp_commit(); }
        {
            const uint32_t base = sb + 8192 + st * 18944;
            const int g = lane >> 3, lr = lane & 7;
#pragma unroll
            for (int ks = 0; ks < 2; ks++) {
                uint32_t bf[4][2];
#pragma unroll
                for (int np = 0; np < 2; np++) {
                    uint32_t ba = base + 10240 + (ks * 16 + (g & 1) * 8 + lr) * 272 +
                                  (wn * 32 + np * 16 + (g >> 1) * 8) * 2;
                    uint32_t r4[4];
                    ldm_x4t(r4, ba);
                    bf[np * 2][0] = r4[0]; bf[np * 2][1] = r4[1];
                    bf[np * 2 + 1][0] = r4[2]; bf[np * 2 + 1][1] = r4[3];
                }
                uint32_t af[2][4];
                ldm_x4(af[0], base + (wm * 64 + (lane & 15)) * 80 + ks * 32 + (lane >> 4) * 16);
#pragma unroll
                for (int mt = 0; mt < 4; mt++) {
                    if (mt < 3)
                        ldm_x4(af[(mt + 1) & 1],
                               base + (wm * 64 + (mt + 1) * 16 + (lane & 15)) * 80 +
                               ks * 32 + (lane >> 4) * 16);
                    const uint32_t* a = af[mt & 1];
#pragma unroll
                    for (int nt = 0; nt < 4; nt++)
                        mmah(acc[mt][nt], a, bf[nt]);
                }
            }
        }
    }
    float* ob = Out + ((size_t)b * TT + q0) * HH;
#pragma unroll
    for (int mt = 0; mt < 4; mt++)
#pragma unroll
        for (int nt = 0; nt < 4; nt++)
#pragma unroll
            for (int h = 0; h < 2; h++) {
                int row = wm * 64 + mt * 16 + (lane >> 2) + h * 8;
                int col = wn * 32 + nt * 8 + (lane & 3) * 2;
                atomicAdd(&ob[(size_t)row * HH + col], acc[mt][nt][h * 2]);
                atomicAdd(&ob[(size_t)row * HH + col + 1], acc[mt][nt][h * 2 + 1]);
            }
}

// ----------------------------------------------------------------------------
extern "C" void kernel_launch(void* const* d_in, const int* in_sizes, int n_in,
                              void* d_out, int out_size) {
    const float* x  = (const float*)d_in[0];
    const float* Wq = (const float*)d_in[1];
    const float* bq = (const float*)d_in[2];
    const float* Wk = (const float*)d_in[3];
    const float* bk = (const float*)d_in[4];
    const float* Wv = (const float*)d_in[5];
    const float* bv = (const float*)d_in[6];
    float* out = (float*)d_out;

    float* pd;
    cudaGetSymbolAddress((void**)&pd, g_d);
    cudaMemsetAsync(pd, 0, BB * TT * sizeof(float));
    cudaMemsetAsync(out, 0, (size_t)out_size * sizeof(float));

    cudaFuncSetAttribute(proj_kernel, cudaFuncAttributeMaxDynamicSharedMemorySize, 61440);
    cudaFuncSetAttribute(scores_kernel, cudaFuncAttributeMaxDynamicSharedMemorySize, 81920);
    cudaFuncSetAttribute(out_kernel, cudaFuncAttributeMaxDynamicSharedMemorySize, 46080);

    convx_kernel<<<BB * TT * DD / 2048, 256>>>(x);
    convw_kernel<<<3 * DD * HH / 256, 256>>>(Wq, Wk, Wv, bq, bk, bv);
    proj_kernel<<<dim3(3, BB * TT / 128), 256, 61440>>>();
    scores_kernel<<<dim3(136, 1, BB), 256, 81920>>>();
    invd_kernel<<<BB * TT / 256, 256>>>();
    out_kernel<<<dim3(8, 16, BB), 256, 46080>>>(out);
}

// round 16
// speedup vs baseline: 1.0314x; 1.0314x over previous
#include <cuda_runtime.h>
#include <cuda_bf16.h>
#include <cuda_fp16.h>
#include <cstdint>

#define BB 8
#define TT 2048
#define DD 1024
#define HH 128
#define STG2 30720
#define STG3 40960

// ---- static scratch (allocation-free) ----
__device__ __half g_xh[BB * TT * DD];                      // x fp16 (A-side)
__device__ __half g_Wh[DD * 384], g_Wl[DD * 384];          // 32*W split [k][w*128+n]
__device__ float g_bias[384];
__device__ __half g_Qh[BB * TT * HH], g_Ql[BB * TT * HH];  // 256*Q split
__device__ __half g_Kh[BB * TT * HH], g_Kl[BB * TT * HH];  // 16*K split
__device__ float g_E[(size_t)BB * TT * TT];                // exp(att), fp32, 0 below diag
__device__ __half g_Vh[BB * TT * HH];                      // V fp16 (written by proj)
__device__ float g_d[BB * TT];

// ---- helpers ----
__device__ __forceinline__ void hsplit(float x, __half& h, __half& l) {
    h = __float2half(x);
    l = __float2half(x - __half2float(h));
}
__device__ __forceinline__ uint32_t s2u(const void* p) {
    uint32_t a;
    asm("{ .reg .u64 t; cvta.to.shared.u64 t, %1; cvt.u32.u64 %0, t; }" : "=r"(a) : "l"(p));
    return a;
}
__device__ __forceinline__ void cpa16(uint32_t dst, const void* src) {
    asm volatile("cp.async.cg.shared.global [%0], [%1], 16;" :: "r"(dst), "l"(src));
}
__device__ __forceinline__ void cp_commit() { asm volatile("cp.async.commit_group;"); }
__device__ __forceinline__ void cp_wait1() { asm volatile("cp.async.wait_group 1;"); }
__device__ __forceinline__ void cp_wait0() { asm volatile("cp.async.wait_group 0;"); }
__device__ __forceinline__ void ldm_x4(uint32_t* r, uint32_t a) {
    asm volatile("ldmatrix.sync.aligned.m8n8.x4.shared.b16 {%0,%1,%2,%3},[%4];"
                 : "=r"(r[0]), "=r"(r[1]), "=r"(r[2]), "=r"(r[3]) : "r"(a));
}
__device__ __forceinline__ void ldm_x4t(uint32_t* r, uint32_t a) {
    asm volatile("ldmatrix.sync.aligned.m8n8.x4.trans.shared.b16 {%0,%1,%2,%3},[%4];"
                 : "=r"(r[0]), "=r"(r[1]), "=r"(r[2]), "=r"(r[3]) : "r"(a));
}
__device__ __forceinline__ void mmah(float* c, const uint32_t* a, const uint32_t* b) {
    asm volatile(
        "mma.sync.aligned.m16n8k16.row.col.f32.f16.f16.f32 "
        "{%0,%1,%2,%3},{%4,%5,%6,%7},{%8,%9},{%0,%1,%2,%3};"
        : "+f"(c[0]), "+f"(c[1]), "+f"(c[2]), "+f"(c[3])
        : "r"(a[0]), "r"(a[1]), "r"(a[2]), "r"(a[3]), "r"(b[0]), "r"(b[1]));
}

// ================= fp16 2-pass pipeline (proj), 2-stage =================
__device__ __forceinline__ void ld_chunk2(const __half* A, int lda,
                                          const __half* Bh, const __half* Bl, int ldb,
                                          uint32_t sb, int tid) {
#pragma unroll
    for (int j = 0; j < 2; j++) {
        int e = tid + j * 256;
        int r = e >> 2, seg = e & 3;
        cpa16(sb + r * 80 + seg * 16, A + (size_t)r * lda + seg * 8);
    }
#pragma unroll
    for (int j = 0; j < 2; j++) {
        int e = tid + j * 256;
        int r = e >> 4, seg = e & 15;
        size_t so = (size_t)r * ldb + seg * 8;
        uint32_t d = sb + 10240 + r * 272 + seg * 16;
        cpa16(d, Bh + so);
        cpa16(d + 10240, Bl + so);
    }
}

__device__ __forceinline__ void compute_chunk2(uint32_t sb, float acc[4][4][4],
                                               int lane, int wm, int wn) {
    const int g = lane >> 3, lr = lane & 7;
#pragma unroll
    for (int ks = 0; ks < 2; ks++) {
        uint32_t bh[4][2], bl[4][2];
#pragma unroll
        for (int np = 0; np < 2; np++) {
            uint32_t ba = sb + 10240 + (ks * 16 + (g & 1) * 8 + lr) * 272 +
                          (wn * 32 + np * 16 + (g >> 1) * 8) * 2;
            uint32_t r[4];
            ldm_x4t(r, ba);
            bh[np * 2][0] = r[0]; bh[np * 2][1] = r[1];
            bh[np * 2 + 1][0] = r[2]; bh[np * 2 + 1][1] = r[3];
            ldm_x4t(r, ba + 10240);
            bl[np * 2][0] = r[0]; bl[np * 2][1] = r[1];
            bl[np * 2 + 1][0] = r[2]; bl[np * 2 + 1][1] = r[3];
        }
        uint32_t af[2][4];
        ldm_x4(af[0], sb + (wm * 64 + (lane & 15)) * 80 + ks * 32 + (lane >> 4) * 16);
#pragma unroll
        for (int mt = 0; mt < 4; mt++) {
            if (mt < 3)
                ldm_x4(af[(mt + 1) & 1],
                       sb + (wm * 64 + (mt + 1) * 16 + (lane & 15)) * 80 + ks * 32 + (lane >> 4) * 16);
            const uint32_t* a = af[mt & 1];
#pragma unroll
            for (int nt = 0; nt < 4; nt++) mmah(acc[mt][nt], a, bh[nt]);
#pragma unroll
            for (int nt = 0; nt < 4; nt++) mmah(acc[mt][nt], a, bl[nt]);
        }
    }
}

__device__ __forceinline__ void gemm_pipe2(const __half* A, int lda,
                                           const __half* Bh, const __half* Bl, int ldb,
                                           int n, size_t aStep, size_t bStep,
                                           uint32_t sb, float acc[4][4][4], int tid) {
    const int lane = tid & 31, wid = tid >> 5;
    const int wm = wid >> 2, wn = wid & 3;
    ld_chunk2(A, lda, Bh, Bl, ldb, sb, tid);
    cp_commit();
    for (int i = 0; i < n; i++) {
        if (i + 1 < n) {
            ld_chunk2(A + (i + 1) * aStep, lda,
                      Bh + (i + 1) * bStep, Bl + (i + 1) * bStep, ldb,
                      sb + ((i + 1) & 1) * STG2, tid);
            cp_commit();
            cp_wait1();
        } else {
            cp_wait0();
        }
        __syncthreads();
        compute_chunk2(sb + (i & 1) * STG2, acc, lane, wm, wn);
        __syncthreads();
    }
}

// ================= fp16 3-pass pipeline (scores), 2-stage =================
__device__ __forceinline__ void ld_chunk3(const __half* Ah, const __half* Al, int lda,
                                          const __half* Bh, const __half* Bl, int ldb,
                                          uint32_t sb, int tid) {
#pragma unroll
    for (int j = 0; j < 2; j++) {
        int e = tid + j * 256;
        int r = e >> 2, seg = e & 3;
        size_t so = (size_t)r * lda + seg * 8;
        uint32_t d = sb + r * 80 + seg * 16;
        cpa16(d, Ah + so);
        cpa16(d + 10240, Al + so);
    }
#pragma unroll
    for (int j = 0; j < 2; j++) {
        int e = tid + j * 256;
        int r = e >> 2, seg = e & 3;
        size_t so = (size_t)r * ldb + seg * 8;
        uint32_t d = sb + 20480 + r * 80 + seg * 16;
        cpa16(d, Bh + so);
        cpa16(d + 10240, Bl + so);
    }
}

__device__ __forceinline__ void compute_chunk3(uint32_t sb, float acc[4][4][4],
                                               int lane, int wm, int wn) {
    const int g = lane >> 3, lr = lane & 7;
#pragma unroll
    for (int ks = 0; ks < 2; ks++) {
        uint32_t bh[4][2], bl[4][2];
#pragma unroll
        for (int np = 0; np < 2; np++) {
            int nrow = wn * 32 + np * 16 + (g >> 1) * 8 + lr;
            uint32_t ba = sb + 20480 + nrow * 80 + ks * 32 + (g & 1) * 16;
            uint32_t r[4];
            ldm_x4(r, ba);
            bh[np * 2][0] = r[0]; bh[np * 2][1] = r[1];
            bh[np * 2 + 1][0] = r[2]; bh[np * 2 + 1][1] = r[3];
            ldm_x4(r, ba + 10240);
            bl[np * 2][0] = r[0]; bl[np * 2][1] = r[1];
            bl[np * 2 + 1][0] = r[2]; bl[np * 2 + 1][1] = r[3];
        }
        uint32_t af[2][4];
        ldm_x4(af[0], sb + (wm * 64 + (lane & 15)) * 80 + ks * 32 + (lane >> 4) * 16);
#pragma unroll
        for (int mt = 0; mt < 4; mt++) {
            if (mt < 3)
                ldm_x4(af[(mt + 1) & 1],
                       sb + (wm * 64 + (mt + 1) * 16 + (lane & 15)) * 80 + ks * 32 + (lane >> 4) * 16);
            const uint32_t* a = af[mt & 1];
#pragma unroll
            for (int nt = 0; nt < 4; nt++) mmah(acc[mt][nt], a, bh[nt]);
#pragma unroll
            for (int nt = 0; nt < 4; nt++) mmah(acc[mt][nt], a, bl[nt]);
        }
        ldm_x4(af[0], sb + 10240 + (wm * 64 + (lane & 15)) * 80 + ks * 32 + (lane >> 4) * 16);
#pragma unroll
        for (int mt = 0; mt < 4; mt++) {
            if (mt < 3)
                ldm_x4(af[(mt + 1) & 1],
                       sb + 10240 + (wm * 64 + (mt + 1) * 16 + (lane & 15)) * 80 + ks * 32 + (lane >> 4) * 16);
            const uint32_t* a = af[mt & 1];
#pragma unroll
            for (int nt = 0; nt < 4; nt++) mmah(acc[mt][nt], a, bh[nt]);
        }
    }
}

__device__ __forceinline__ void gemm_pipe3(const __half* Ah, const __half* Al, int lda,
                                           const __half* Bh, const __half* Bl, int ldb,
                                           int n, size_t aStep, size_t bStep,
                                           uint32_t sb, float acc[4][4][4], int tid) {
    const int lane = tid & 31, wid = tid >> 5;
    const int wm = wid >> 2, wn = wid & 3;
    ld_chunk3(Ah, Al, lda, Bh, Bl, ldb, sb, tid);
    cp_commit();
    for (int i = 0; i < n; i++) {
        if (i + 1 < n) {
            ld_chunk3(Ah + (i + 1) * aStep, Al + (i + 1) * aStep, lda,
                      Bh + (i + 1) * bStep, Bl + (i + 1) * bStep, ldb,
                      sb + ((i + 1) & 1) * STG3, tid);
            cp_commit();
            cp_wait1();
        } else {
            cp_wait0();
        }
        __syncthreads();
        compute_chunk3(sb + (i & 1) * STG3, acc, lane, wm, wn);
        __syncthreads();
    }
}

// ---- convert kernels ----
__global__ void convx_kernel(const float* __restrict__ x) {
    size_t i = ((size_t)blockIdx.x * 256 + threadIdx.x) * 8;
#pragma unroll
    for (int j = 0; j < 2; j++) {
        float4 v = *(const float4*)&x[i + j * 4];
        *(__half2*)&g_xh[i + j * 4] = {__float2half(v.x), __float2half(v.y)};
        *(__half2*)&g_xh[i + j * 4 + 2] = {__float2half(v.z), __float2half(v.w)};
    }
}
__global__ void convw_kernel(const float* __restrict__ Wq, const float* __restrict__ Wk,
                             const float* __restrict__ Wv, const float* __restrict__ bq,
                             const float* __restrict__ bk, const float* __restrict__ bv) {
    int i = blockIdx.x * 256 + threadIdx.x;
    int w = i / (DD * HH), rem = i % (DD * HH);
    int r = rem / HH, c = rem % HH;
    const float* W = (w == 0) ? Wq : (w == 1) ? Wk : Wv;
    float v = W[(size_t)r * HH + c] * 32.0f;
    __half h, l;
    hsplit(v, h, l);
    g_Wh[(size_t)r * 384 + w * 128 + c] = h;
    g_Wl[(size_t)r * 384 + w * 128 + c] = l;
    if (i < 384)
        g_bias[i] = (i < 128) ? bq[i] : (i < 256) ? bk[i - 128] : bv[i - 256];
}

// ---- stage 1: projections (fp16 2-pass, 2-stage) ----
__global__ void __launch_bounds__(256, 2) proj_kernel() {
    extern __shared__ char sm[];
    const uint32_t sb = s2u(sm);
    const int tid = threadIdx.x, lane = tid & 31, wid = tid >> 5;
    const int wm = wid >> 2, wn = wid & 3;
    const int w = blockIdx.x, m0 = blockIdx.y * 128;
    float acc[4][4][4] = {};
    gemm_pipe2(g_xh + (size_t)m0 * DD, DD,
               g_Wh + w * 128, g_Wl + w * 128, 384,
               32, 32, (size_t)32 * 384, sb, acc, tid);
    const float* bias = g_bias + w * 128;
#pragma unroll
    for (int mt = 0; mt < 4; mt++)
#pragma unroll
        for (int nt = 0; nt < 4; nt++)
#pragma unroll
            for (int h = 0; h < 2; h++) {
                int row = wm * 64 + mt * 16 + (lane >> 2) + h * 8;
                int col = wn * 32 + nt * 8 + (lane & 3) * 2;
                size_t gm = (size_t)(m0 + row);
                float v0 = acc[mt][nt][h * 2] * 0.03125f + bias[col];      // /32
                float v1 = acc[mt][nt][h * 2 + 1] * 0.03125f + bias[col + 1];
                if (w == 2) {
                    *(__half2*)&g_Vh[gm * HH + col] = {__float2half(v0), __float2half(v1)};
                } else if (w == 0) {
                    __half h0, l0, h1, l1;
                    hsplit(v0 * 256.0f, h0, l0);
                    hsplit(v1 * 256.0f, h1, l1);
                    *(__half2*)&g_Qh[gm * HH + col] = {h0, h1};
                    *(__half2*)&g_Ql[gm * HH + col] = {l0, l1};
                } else {
                    __half h0, l0, h1, l1;
                    hsplit(v0 * 16.0f, h0, l0);
                    hsplit(v1 * 16.0f, h1, l1);
                    *(__half2*)&g_Kh[gm * HH + col] = {h0, h1};
                    *(__half2*)&g_Kl[gm * HH + col] = {l0, l1};
                }
            }
}

// ---- stage 2: scores (fp16 3-pass; E fp32; compacted upper-tri grid) ----
__global__ void __launch_bounds__(256, 2) scores_kernel() {
    const int t = blockIdx.x, b = blockIdx.z;
    int kT = (int)((sqrtf(8.0f * t + 1.0f) - 1.0f) * 0.5f);
    while (kT * (kT + 1) / 2 > t) kT--;
    while ((kT + 1) * (kT + 2) / 2 <= t) kT++;
    const int qT = t - kT * (kT + 1) / 2;
    extern __shared__ char sm[];
    const uint32_t sb = s2u(sm);
    const int tid = threadIdx.x, lane = tid & 31, wid = tid >> 5;
    const int wm = wid >> 2, wn = wid & 3;
    const int q0 = qT * 128, k0 = kT * 128;
    const size_t mq = (size_t)b * TT + q0, mk = (size_t)b * TT + k0;
    float acc[4][4][4] = {};
    gemm_pipe3(g_Qh + mq * HH, g_Ql + mq * HH, HH,
               g_Kh + mk * HH, g_Kl + mk * HH, HH,
               4, 32, 32, sb, acc, tid);
    float* se = (float*)sm;  // [128][136]
#pragma unroll
    for (int mt = 0; mt < 4; mt++)
#pragma unroll
        for (int nt = 0; nt < 4; nt++)
#pragma unroll
            for (int h = 0; h < 2; h++) {
                int row = wm * 64 + mt * 16 + (lane >> 2) + h * 8;
                int col = wn * 32 + nt * 8 + (lane & 3) * 2;
                int q = q0 + row;
                float a0 = acc[mt][nt][h * 2] * 2.44140625e-4f;        // /(256*16)
                float a1 = acc[mt][nt][h * 2 + 1] * 2.44140625e-4f;
                se[row * 136 + col] = (q <= k0 + col) ? __expf(a0) : 0.f;
                se[row * 136 + col + 1] = (q <= k0 + col + 1) ? __expf(a1) : 0.f;
            }
    __syncthreads();
    if (tid < 128) {
        float s = 0.f;
#pragma unroll 8
        for (int r = 0; r < 128; r++) s += se[r * 136 + tid];
        atomicAdd(&g_d[b * TT + k0 + tid], s);
    }
    float* Eb = g_E + (size_t)b * TT * TT;
#pragma unroll 4
    for (int i = 0; i < 16; i++) {
        int e = tid + i * 256;
        int q = e >> 5, c4 = (e & 31) * 4;
        *(float4*)&Eb[(size_t)(q0 + q) * TT + k0 + c4] = *(float4*)&se[q * 136 + c4];
    }
}

// ---- stage 3: out = (E/d) @ V, 1-pass fp16, 4-way split-k, atomics ----
// smem: invd[2048]f @0 (8192B); 2 stages of (A 10240 + B 8704) @8192, stride 18944.
__global__ void __launch_bounds__(256, 2) out_kernel(float* __restrict__ Out) {
    const int seg = blockIdx.x, qT = blockIdx.y, b = blockIdx.z;
    extern __shared__ char sm[];
    const uint32_t sb = s2u(sm);
    const int tid = threadIdx.x, lane = tid & 31, wid = tid >> 5;
    const int wm = wid >> 2, wn = wid & 3;
    const int q0 = qT * 128;
    const int c0 = q0 / 32 + seg;
    const int nch = (TT - q0) / 32;
    const int nIter = (nch - seg + 3) / 4;
    if (nIter <= 0) return;

    float* invd_s = (float*)sm;
    for (int i = tid; i < TT; i += 256) invd_s[i] = 1.0f / g_d[b * TT + i];

    const float* Eb = g_E + ((size_t)b * TT + q0) * TT;
    const __half* Vb = g_Vh + (size_t)b * TT * HH;

    float er[2][8];
    auto ldE = [&](int i) {
        int kk = (c0 + i * 4) * 32;
#pragma unroll
        for (int j = 0; j < 2; j++) {
            int e = tid + j * 256;
            int r = e >> 2, s8 = (e & 3) * 8;
            const float* p = Eb + (size_t)r * TT + kk + s8;
            float4 v0 = *(const float4*)p;
            float4 v1 = *(const float4*)(p + 4);
            er[j][0] = v0.x; er[j][1] = v0.y; er[j][2] = v0.z; er[j][3] = v0.w;
            er[j][4] = v1.x; er[j][5] = v1.y; er[j][6] = v1.z; er[j][7] = v1.w;
        }
    };
    auto ldV = [&](int i, int st) {
#pragma unroll
        for (int j = 0; j < 2; j++) {
            int e = tid + j * 256;
            int r = e >> 4, sg = e & 15;
            cpa16(sb + 8192 + st * 18944 + 10240 + r * 272 + sg * 16,
                  Vb + ((size_t)((c0 + i * 4) * 32 + r)) * HH + sg * 8);
        }
    };

    ldE(0);
    ldV(0, 0);
    cp_commit();

    float acc[4][4][4] = {};
    for (int i = 0; i < nIter; i++) {
        const int st = i & 1;
        cp_wait0();
        __syncthreads();
        {
            int kk = (c0 + i * 4) * 32;
#pragma unroll
            for (int j = 0; j < 2; j++) {
                int e = tid + j * 256;
                int r = e >> 2, s8 = (e & 3) * 8;
                __half2 hx[4];
#pragma unroll
                for (int p2 = 0; p2 < 4; p2++) {
                    float a0 = er[j][p2 * 2] * invd_s[kk + s8 + p2 * 2];
                    float a1 = er[j][p2 * 2 + 1] * invd_s[kk + s8 + p2 * 2 + 1];
                    hx[p2] = __floats2half2_rn(a0, a1);
                }
                *(uint4*)(sm + 8192 + st * 18944 + r * 80 + s8 * 2) = *(uint4*)hx;
            }
        }
        if (i + 1 < nIter) ldE(i + 1);
        __syncthreads();
        if (i + 1 < nIter) { ldV(i + 1, st ^ 1); cp_commit(); }
        {
            const uint32_t base = sb + 8192 + st * 18944;
            const int g = lane >> 3, lr = lane & 7;
#pragma unroll
            for (int ks = 0; ks < 2; ks++) {
                uint32_t bf[4][2];
#pragma unroll
                for (int np = 0; np < 2; np++) {
                    uint32_t ba = base + 10240 + (ks * 16 + (g & 1) * 8 + lr) * 272 +
                                  (wn * 32 + np * 16 + (g >> 1) * 8) * 2;
                    uint32_t r4[4];
                    ldm_x4t(r4, ba);
                    bf[np * 2][0] = r4[0]; bf[np * 2][1] = r4[1];
                    bf[np * 2 + 1][0] = r4[2]; bf[np * 2 + 1][1] = r4[3];
                }
                uint32_t af[2][4];
                ldm_x4(af[0], base + (wm * 64 + (lane & 15)) * 80 + ks * 32 + (lane >> 4) * 16);
#pragma unroll
                for (int mt = 0; mt < 4; mt++) {
                    if (mt < 3)
                        ldm_x4(af[(mt + 1) & 1],
                               base + (wm * 64 + (mt + 1) * 16 + (lane & 15)) * 80 +
                               ks * 32 + (lane >> 4) * 16);
                    const uint32_t* a = af[mt & 1];
#pragma unroll
                    for (int nt = 0; nt < 4; nt++)
                        mmah(acc[mt][nt], a, bf[nt]);
                }
            }
        }
    }
    float* ob = Out + ((size_t)b * TT + q0) * HH;
#pragma unroll
    for (int mt = 0; mt < 4; mt++)
#pragma unroll
        for (int nt = 0; nt < 4; nt++)
#pragma unroll
            for (int h = 0; h < 2; h++) {
                int row = wm * 64 + mt * 16 + (lane >> 2) + h * 8;
                int col = wn * 32 + nt * 8 + (lane & 3) * 2;
                atomicAdd(&ob[(size_t)row * HH + col], acc[mt][nt][h * 2]);
                atomicAdd(&ob[(size_t)row * HH + col + 1], acc[mt][nt][h * 2 + 1]);
            }
}

// ----------------------------------------------------------------------------
extern "C" void kernel_launch(void* const* d_in, const int* in_sizes, int n_in,
                              void* d_out, int out_size) {
    const float* x  = (const float*)d_in[0];
    const float* Wq = (const float*)d_in[1];
    const float* bq = (const float*)d_in[2];
    const float* Wk = (const float*)d_in[3];
    const float* bk = (const float*)d_in[4];
    const float* Wv = (const float*)d_in[5];
    const float* bv = (const float*)d_in[6];
    float* out = (float*)d_out;

    float* pd;
    cudaGetSymbolAddress((void**)&pd, g_d);
    cudaMemsetAsync(pd, 0, BB * TT * sizeof(float));
    cudaMemsetAsync(out, 0, (size_t)out_size * sizeof(float));

    cudaFuncSetAttribute(proj_kernel, cudaFuncAttributeMaxDynamicSharedMemorySize, 61440);
    cudaFuncSetAttribute(scores_kernel, cudaFuncAttributeMaxDynamicSharedMemorySize, 81920);
    cudaFuncSetAttribute(out_kernel, cudaFuncAttributeMaxDynamicSharedMemorySize, 46080);

    convx_kernel<<<BB * TT * DD / 2048, 256>>>(x);
    convw_kernel<<<3 * DD * HH / 256, 256>>>(Wq, Wk, Wv, bq, bk, bv);
    proj_kernel<<<dim3(3, BB * TT / 128), 256, 61440>>>();
    scores_kernel<<<dim3(136, 1, BB), 256, 81920>>>();
    out_kernel<<<dim3(4, 16, BB), 256, 46080>>>(out);
}